// round 14
// baseline (speedup 1.0000x reference)
#include <cuda_runtime.h>
#include <cuda_fp16.h>
#include <cstddef>
#include <cstdint>

#define N_NODES 8192
#define IN_DIM  512
#define OUT_DIM 64
#define ALPHA   0.2f
#define LOG2E   1.4426950408889634f

// ---------------- scratch (no allocations allowed) ----------------
__device__ __align__(16) float    g_h [N_NODES * OUT_DIM];      // h = X @ W (f32)
__device__ __align__(16) __half   g_hT[OUT_DIM * N_NODES];      // h^T, fp16
__device__ __align__(16) uint32_t g_WT[OUT_DIM * IN_DIM / 2];   // W^T fp16 pair-packed
__device__ __align__(16) float    g_s1[N_NODES];
__device__ __align__(16) float    g_s2[N_NODES];
__device__ __align__(16) float    g_pD [2 * N_NODES * OUT_DIM]; // [jh][row][col]
__device__ __align__(16) float    g_pes[2 * N_NODES];           // [jh][row]
__device__ unsigned               g_s2max_u;                    // enc(max_j s2)

__device__ __forceinline__ uint32_t pack_f16(float lo, float hi) {
    uint32_t r;
    asm("cvt.rn.f16x2.f32 %0, %1, %2;" : "=r"(r) : "f"(hi), "f"(lo));
    return r;
}
__device__ __forceinline__ float ex2f(float x) {
    float r;
    asm("ex2.approx.f32 %0, %1;" : "=f"(r) : "f"(x));
    return r;
}
__device__ __forceinline__ unsigned encf(float f) {
    unsigned u = __float_as_uint(f);
    return (u & 0x80000000u) ? ~u : (u | 0x80000000u);
}
__device__ __forceinline__ float decf(unsigned u) {
    return (u & 0x80000000u) ? __uint_as_float(u & 0x7FFFFFFFu)
                             : __uint_as_float(~u);
}

// ---------------------------------------------------------------------------
// Kernel 0: pack W^T into fp16 pairs along k. Also resets g_s2max_u.
// ---------------------------------------------------------------------------
__global__ __launch_bounds__(256) void wt_prep_kernel(const float* __restrict__ W) {
    const int t = threadIdx.x;
    const int d = t & 63, k2 = blockIdx.x * 4 + (t >> 6);
    float lo = W[(size_t)(2 * k2) * OUT_DIM + d];
    float hi = W[(size_t)(2 * k2 + 1) * OUT_DIM + d];
    g_WT[(size_t)d * (IN_DIM / 2) + k2] = pack_f16(lo, hi);
    if (blockIdx.x == 0 && t == 0) g_s2max_u = 0u;
}

// ---------------------------------------------------------------------------
// Kernel 1: h = X @ W on fp16 mma.sync.m16n8k16 (unchanged from R13).
// ---------------------------------------------------------------------------
#define GXS_OFF  16384
#define GXS_STR  36
#define GSMEM_W  (16384 + 2 * 64 * GXS_STR)
#define GSMEM_B  (GSMEM_W * 4)

__global__ __launch_bounds__(256) void gemm_f16_kernel(const float* __restrict__ X) {
    extern __shared__ __align__(16) uint32_t dsm[];
    uint32_t* B_sm = dsm;
    uint32_t* Xs   = dsm + GXS_OFF;

    const int t = threadIdx.x, lane = t & 31, wid = t >> 5;
    const int grp = wid >> 2, woff = (wid & 3) * 16;
    const int g = lane >> 2, q = lane & 3;
    const int i0 = blockIdx.x * 64;
    const int sn = t >> 2, sq = t & 3;

#pragma unroll
    for (int cc = 0; cc < 8; cc++) {
        const int c8 = sq + cc * 4;
        const uint4* src = (const uint4*)(g_WT + (size_t)sn * (IN_DIM / 2) + c8 * 8);
        uint4 v0 = src[0], v1 = src[1];
        uint32_t* dst = B_sm + c8 * 512 + sn * 8;
        dst[0] = v0.x; dst[2] = v0.y; dst[4] = v0.z; dst[6] = v0.w;
        dst[1] = v1.x; dst[3] = v1.y; dst[5] = v1.z; dst[7] = v1.w;
    }

    float c[8][4];
#pragma unroll
    for (int tl = 0; tl < 8; tl++)
#pragma unroll
        for (int k = 0; k < 4; k++) c[tl][k] = 0.f;

    for (int it = 0; it < 4; it++) {
        __syncthreads();
#pragma unroll
        for (int qq = 0; qq < 8; qq++) {
            const int idx = t + 256 * qq;
            const int seg = idx >> 10;
            const int r   = (idx >> 4) & 63;
            const int c4  = (idx & 15) * 4;
            const float4 v = *(const float4*)&X[(size_t)(i0 + r) * IN_DIM
                                                + seg * 256 + it * 64 + c4];
            uint32_t* xd = Xs + (seg * 64 + r) * GXS_STR + (c4 >> 1);
            xd[0] = pack_f16(v.x, v.y);
            xd[1] = pack_f16(v.z, v.w);
        }
        __syncthreads();

        const uint32_t* xrA = Xs + (grp * 64 + woff + g) * GXS_STR;
        const uint32_t* xrB = xrA + 8 * GXS_STR;
#pragma unroll
        for (int s = 0; s < 4; s++) {
            const int kw = s * 8;
            const uint32_t a0 = xrA[kw + q];
            const uint32_t a2 = xrA[kw + 4 + q];
            const uint32_t a1 = xrB[kw + q];
            const uint32_t a3 = xrB[kw + 4 + q];
            const int gstep = grp * 16 + it * 4 + s;
            const uint32_t* Bp = B_sm + gstep * 512 + g * 8 + q * 2;
#pragma unroll
            for (int tl = 0; tl < 8; tl++) {
                uint2 bb = *(const uint2*)(Bp + tl * 64);
                asm volatile(
                    "mma.sync.aligned.m16n8k16.row.col.f32.f16.f16.f32 "
                    "{%0,%1,%2,%3}, {%4,%5,%6,%7}, {%8,%9}, {%0,%1,%2,%3};"
                    : "+f"(c[tl][0]), "+f"(c[tl][1]), "+f"(c[tl][2]), "+f"(c[tl][3])
                    : "r"(a0), "r"(a1), "r"(a2), "r"(a3), "r"(bb.x), "r"(bb.y));
            }
        }
    }

    __syncthreads();
    float* red = (float*)dsm;
    if (grp == 1) {
        float* p = red + ((size_t)((wid - 4) * 32 + lane)) * 32;
#pragma unroll
        for (int tl = 0; tl < 8; tl++)
#pragma unroll
            for (int k = 0; k < 4; k++) p[tl * 4 + k] = c[tl][k];
    }
    __syncthreads();
    if (grp == 0) {
        const float* p = red + ((size_t)(wid * 32 + lane)) * 32;
#pragma unroll
        for (int tl = 0; tl < 8; tl++)
#pragma unroll
            for (int k = 0; k < 4; k++) c[tl][k] += p[tl * 4 + k];
        const int iA = i0 + woff + g, iB = iA + 8;
#pragma unroll
        for (int tl = 0; tl < 8; tl++) {
            const int col = tl * 8 + 2 * q;
            *(float2*)&g_h[(size_t)iA * OUT_DIM + col] = make_float2(c[tl][0], c[tl][1]);
            *(float2*)&g_h[(size_t)iB * OUT_DIM + col] = make_float2(c[tl][2], c[tl][3]);
        }
    }
}

// ---------------------------------------------------------------------------
// Kernel 2: SMEM transpose h -> g_hT (fp16), s1/s2 scores, global max(s2).
// ---------------------------------------------------------------------------
__global__ __launch_bounds__(256) void score_T_kernel(const float* __restrict__ a) {
    __shared__ __align__(16) float hs[64][68];
    const int t = threadIdx.x, i0 = blockIdx.x * 64;
    {
        const int r = t >> 2, c0 = (t & 3) * 16;
#pragma unroll
        for (int q = 0; q < 4; q++)
            *(float4*)&hs[r][c0 + q * 4] =
                *(const float4*)&g_h[(size_t)(i0 + r) * OUT_DIM + c0 + q * 4];
    }
    __syncthreads();
    {
        const int d = t >> 2, ibs = (t & 3) * 16;
        uint32_t* dst = (uint32_t*)g_hT + ((size_t)d * N_NODES + i0 + ibs) / 2;
#pragma unroll
        for (int k = 0; k < 8; k++)
            dst[k] = pack_f16(hs[ibs + 2 * k][d], hs[ibs + 2 * k + 1][d]);
    }
    {
        const int w = t >> 5, lane = t & 31;
#pragma unroll
        for (int rr = 0; rr < 8; rr++) {
            const int row = w * 8 + rr;
            float v0 = hs[row][lane], v1 = hs[row][lane + 32];
            float p1 = v0 * a[lane]      + v1 * a[lane + 32];
            float p2 = v0 * a[64 + lane] + v1 * a[96 + lane];
#pragma unroll
            for (int off = 16; off; off >>= 1) {
                p1 += __shfl_down_sync(0xffffffffu, p1, off);
                p2 += __shfl_down_sync(0xffffffffu, p2, off);
            }
            if (lane == 0) {
                g_s1[i0 + row] = p1;
                g_s2[i0 + row] = p2;
                atomicMax(&g_s2max_u, encf(p2));
            }
        }
    }
}

// ---------------------------------------------------------------------------
// Kernel 3: fused masked-softmax attention, fp16 mma.sync.m16n8k16.
// CHANGE vs R13: Adj loaded DIRECTLY into fragment lanes (16 int2, MLP=16,
// 32B-sector coalesced, zero over-fetch) — no ballots, no bit extraction.
// ---------------------------------------------------------------------------
__global__ __launch_bounds__(256, 2) void attn_f16_kernel(const int* __restrict__ Adj) {
    __shared__ __align__(16) float smem_buf[4352];
    uint32_t* B_sm  = (uint32_t*)smem_buf;
    float*    s2_sm = smem_buf + 4096;

    const int t = threadIdx.x, lane = t & 31, wid = t >> 5;
    const int ib = blockIdx.x >> 1, jh = blockIdx.x & 1;
    const int i0 = ib * 64, jbase = jh * 4096;
    const int grp = wid >> 2, woff = (wid & 3) * 16;
    const int g = lane >> 2, l4 = lane & 3;
    const int iA = i0 + woff + g, iB = iA + 8;

    const float s1a = g_s1[iA] * LOG2E;
    const float s1b = g_s1[iB] * LOG2E;
    const float s2m = decf(g_s2max_u) * LOG2E;
    float bA = s1a + s2m; bA = fmaxf(bA, ALPHA * bA);
    float bB = s1b + s2m; bB = fmaxf(bB, ALPHA * bB);
    const float kA = fmaxf(0.f, bA - 14.f);
    const float kB = fmaxf(0.f, bB - 14.f);
    const float aA = s1a - kA, cA = fmaf(ALPHA, s1a, -kA);
    const float aB = s1b - kB, cB = fmaf(ALPHA, s1b, -kB);

    float c[8][4];
#pragma unroll
    for (int tl = 0; tl < 8; tl++)
#pragma unroll
        for (int k = 0; k < 4; k++) c[tl][k] = 0.f;
    float esA = 0.f, esB = 0.f;

    const uint32_t* hT32 = (const uint32_t*)g_hT;
    const int sn = t >> 2, sq = t & 3;

    // lane-local Adj row pointers (fragment-aligned: cols 2*l4 + 16s (+8))
    const int* rAptr = Adj + (size_t)iA * N_NODES + jbase + grp * 64 + 2 * l4;
    const int* rBptr = Adj + (size_t)iB * N_NODES + jbase + grp * 64 + 2 * l4;

    for (int ch = 0; ch < 32; ch++) {
        const int j0 = jbase + ch * 128;
        const int joff = ch * 128;

        // ---- direct Adj prefetch: 16 int2, MLP=16 ----
        int2 vA[8], vB[8];
#pragma unroll
        for (int s = 0; s < 4; s++) {
            vA[2 * s]     = *(const int2*)(rAptr + joff + 16 * s);
            vA[2 * s + 1] = *(const int2*)(rAptr + joff + 16 * s + 8);
            vB[2 * s]     = *(const int2*)(rBptr + joff + 16 * s);
            vB[2 * s + 1] = *(const int2*)(rBptr + joff + 16 * s + 8);
        }
        __syncthreads();   // previous chunk's B consumption complete

        // ---- stage B: h^T fp16 pairs in fragment order; s2 (pre-scaled) ----
#pragma unroll
        for (int cc = 0; cc < 2; cc++) {
            const int c8 = sq + cc * 4;
            const uint4* src = (const uint4*)(hT32 + (size_t)sn * (N_NODES / 2)
                                              + (size_t)(j0 + c8 * 16) / 2);
            uint4 v0 = src[0], v1 = src[1];
            uint32_t* dst = B_sm + c8 * 512 + sn * 8;
            dst[0] = v0.x; dst[2] = v0.y; dst[4] = v0.z; dst[6] = v0.w;
            dst[1] = v1.x; dst[3] = v1.y; dst[5] = v1.z; dst[7] = v1.w;
        }
        if (t < 128) s2_sm[t] = g_s2[j0 + t] * LOG2E;
        __syncthreads();

        // ---- 4 steps of 16 j: E in A-fragment regs, 8 MMAs over d ----
#pragma unroll
        for (int s = 0; s < 4; s++) {
            const float* s2p = s2_sm + grp * 64 + s * 16;
            float2 sA = *(const float2*)(s2p + 2 * l4);
            float2 sB = *(const float2*)(s2p + 2 * l4 + 8);

            float e00, e01, e02, e03, e10, e11, e12, e13;
            e00 = vA[2*s].x   ? ex2f(fmaxf(aA + sA.x, fmaf(ALPHA, sA.x, cA))) : 0.f;
            e01 = vA[2*s].y   ? ex2f(fmaxf(aA + sA.y, fmaf(ALPHA, sA.y, cA))) : 0.f;
            e02 = vA[2*s+1].x ? ex2f(fmaxf(aA + sB.x, fmaf(ALPHA, sB.x, cA))) : 0.f;
            e03 = vA[2*s+1].y ? ex2f(fmaxf(aA + sB.y, fmaf(ALPHA, sB.y, cA))) : 0.f;
            e10 = vB[2*s].x   ? ex2f(fmaxf(aB + sA.x, fmaf(ALPHA, sA.x, cB))) : 0.f;
            e11 = vB[2*s].y   ? ex2f(fmaxf(aB + sA.y, fmaf(ALPHA, sA.y, cB))) : 0.f;
            e12 = vB[2*s+1].x ? ex2f(fmaxf(aB + sB.x, fmaf(ALPHA, sB.x, cB))) : 0.f;
            e13 = vB[2*s+1].y ? ex2f(fmaxf(aB + sB.y, fmaf(ALPHA, sB.y, cB))) : 0.f;
            esA += (e00 + e01) + (e02 + e03);
            esB += (e10 + e11) + (e12 + e13);

            const uint32_t a0 = pack_f16(e00, e01);
            const uint32_t a1 = pack_f16(e10, e11);
            const uint32_t a2 = pack_f16(e02, e03);
            const uint32_t a3 = pack_f16(e12, e13);

            const uint32_t* Bp = B_sm + (grp * 4 + s) * 512 + g * 8 + l4 * 2;
#pragma unroll
            for (int tl = 0; tl < 8; tl++) {
                uint2 bb = *(const uint2*)(Bp + tl * 64);
                asm volatile(
                    "mma.sync.aligned.m16n8k16.row.col.f32.f16.f16.f32 "
                    "{%0,%1,%2,%3}, {%4,%5,%6,%7}, {%8,%9}, {%0,%1,%2,%3};"
                    : "+f"(c[tl][0]), "+f"(c[tl][1]), "+f"(c[tl][2]), "+f"(c[tl][3])
                    : "r"(a0), "r"(a1), "r"(a2), "r"(a3), "r"(bb.x), "r"(bb.y));
            }
        }
    }

    // ---- merge grp1 into grp0 via SMEM (alias over staging area) ----
    __syncthreads();
    float* red = smem_buf;
    if (grp == 1) {
        float* p = red + ((size_t)((wid - 4) * 32 + lane)) * 34;
#pragma unroll
        for (int tl = 0; tl < 8; tl++)
#pragma unroll
            for (int k = 0; k < 4; k++) p[tl * 4 + k] = c[tl][k];
        p[32] = esA; p[33] = esB;
    }
    __syncthreads();
    if (grp == 0) {
        const float* p = red + ((size_t)(wid * 32 + lane)) * 34;
#pragma unroll
        for (int tl = 0; tl < 8; tl++)
#pragma unroll
            for (int k = 0; k < 4; k++) c[tl][k] += p[tl * 4 + k];
        esA += p[32]; esB += p[33];

        esA += __shfl_xor_sync(0xffffffffu, esA, 1);
        esA += __shfl_xor_sync(0xffffffffu, esA, 2);
        esB += __shfl_xor_sync(0xffffffffu, esB, 1);
        esB += __shfl_xor_sync(0xffffffffu, esB, 2);
        if (l4 == 0) {
            g_pes[(size_t)jh * N_NODES + iA] = esA;
            g_pes[(size_t)jh * N_NODES + iB] = esB;
        }
        float* outA = g_pD + ((size_t)jh * N_NODES + iA) * OUT_DIM;
        float* outB = g_pD + ((size_t)jh * N_NODES + iB) * OUT_DIM;
#pragma unroll
        for (int tl = 0; tl < 8; tl++) {
            *(float2*)(outA + tl * 8 + 2 * l4) = make_float2(c[tl][0], c[tl][1]);
            *(float2*)(outB + tl * 8 + 2 * l4) = make_float2(c[tl][2], c[tl][3]);
        }
    }
}

// ---------------------------------------------------------------------------
// Kernel 4: merge j-halves and normalize. Warp per row.
// ---------------------------------------------------------------------------
__global__ __launch_bounds__(256) void merge_kernel(float* __restrict__ out) {
    const int row  = blockIdx.x * 8 + (threadIdx.x >> 5);
    const int lane = threadIdx.x & 31;
    const float inv = 1.f / (g_pes[row] + g_pes[N_NODES + row]);
    const size_t o = (size_t)row * OUT_DIM + lane * 2;
    float2 v0 = *(const float2*)(g_pD + o);
    float2 v1 = *(const float2*)(g_pD + (size_t)N_NODES * OUT_DIM + o);
    *(float2*)(out + o) = make_float2((v0.x + v1.x) * inv, (v0.y + v1.y) * inv);
}

// ---------------------------------------------------------------------------
extern "C" void kernel_launch(void* const* d_in, const int* in_sizes, int n_in,
                              void* d_out, int out_size) {
    const float* X = nullptr; const int* Adj = nullptr;
    const float* W = nullptr; const float* a = nullptr;
    for (int k = 0; k < n_in; k++) {
        switch (in_sizes[k]) {
            case N_NODES * IN_DIM:  X   = (const float*)d_in[k]; break;
            case N_NODES * N_NODES: Adj = (const int*)d_in[k];   break;
            case IN_DIM * OUT_DIM:  W   = (const float*)d_in[k]; break;
            case 2 * OUT_DIM:       a   = (const float*)d_in[k]; break;
        }
    }

    static bool attr_set = false;
    if (!attr_set) {
        cudaFuncSetAttribute(gemm_f16_kernel,
                             cudaFuncAttributeMaxDynamicSharedMemorySize, GSMEM_B);
        attr_set = true;
    }

    wt_prep_kernel<<<64, 256>>>(W);
    gemm_f16_kernel<<<N_NODES / 64, 256, GSMEM_B>>>(X);
    score_T_kernel<<<N_NODES / 64, 256>>>(a);
    attn_f16_kernel<<<256, 256>>>(Adj);
    merge_kernel<<<N_NODES / 8, 256>>>((float*)d_out);
}

// round 15
// speedup vs baseline: 1.0170x; 1.0170x over previous
#include <cuda_runtime.h>
#include <cuda_fp16.h>
#include <cstddef>
#include <cstdint>

#define N_NODES 8192
#define IN_DIM  512
#define OUT_DIM 64
#define ALPHA   0.2f
#define LOG2E   1.4426950408889634f

// ---------------- scratch (no allocations allowed) ----------------
__device__ __align__(16) float    g_h [N_NODES * OUT_DIM];      // h = X @ W (f32)
__device__ __align__(16) __half   g_hT[OUT_DIM * N_NODES];      // h^T, fp16
__device__ __align__(16) uint32_t g_WT[OUT_DIM * IN_DIM / 2];   // W^T fp16 pair-packed
__device__ __align__(16) float    g_s1[N_NODES];
__device__ __align__(16) float    g_s2[N_NODES];
__device__ __align__(16) float    g_pD [2 * N_NODES * OUT_DIM]; // [jh][row][col]
__device__ __align__(16) float    g_pes[2 * N_NODES];           // [jh][row]
__device__ unsigned               g_s2max_u;                    // enc(max_j s2)

__device__ __forceinline__ uint32_t pack_f16(float lo, float hi) {
    uint32_t r;
    asm("cvt.rn.f16x2.f32 %0, %1, %2;" : "=r"(r) : "f"(hi), "f"(lo));
    return r;
}
__device__ __forceinline__ float ex2f(float x) {
    float r;
    asm("ex2.approx.f32 %0, %1;" : "=f"(r) : "f"(x));
    return r;
}
__device__ __forceinline__ unsigned encf(float f) {
    unsigned u = __float_as_uint(f);
    return (u & 0x80000000u) ? ~u : (u | 0x80000000u);
}
__device__ __forceinline__ float decf(unsigned u) {
    return (u & 0x80000000u) ? __uint_as_float(u & 0x7FFFFFFFu)
                             : __uint_as_float(~u);
}

// ---------------------------------------------------------------------------
// Kernel 0: pack W^T into fp16 pairs along k. Also resets g_s2max_u.
// ---------------------------------------------------------------------------
__global__ __launch_bounds__(256) void wt_prep_kernel(const float* __restrict__ W) {
    const int t = threadIdx.x;
    const int d = t & 63, k2 = blockIdx.x * 4 + (t >> 6);
    float lo = W[(size_t)(2 * k2) * OUT_DIM + d];
    float hi = W[(size_t)(2 * k2 + 1) * OUT_DIM + d];
    g_WT[(size_t)d * (IN_DIM / 2) + k2] = pack_f16(lo, hi);
    if (blockIdx.x == 0 && t == 0) g_s2max_u = 0u;
}

// ---------------------------------------------------------------------------
// Kernel 1: h = X @ W on fp16 mma.sync.m16n8k16 (unchanged from R13).
// ---------------------------------------------------------------------------
#define GXS_OFF  16384
#define GXS_STR  36
#define GSMEM_W  (16384 + 2 * 64 * GXS_STR)
#define GSMEM_B  (GSMEM_W * 4)

__global__ __launch_bounds__(256) void gemm_f16_kernel(const float* __restrict__ X) {
    extern __shared__ __align__(16) uint32_t dsm[];
    uint32_t* B_sm = dsm;
    uint32_t* Xs   = dsm + GXS_OFF;

    const int t = threadIdx.x, lane = t & 31, wid = t >> 5;
    const int grp = wid >> 2, woff = (wid & 3) * 16;
    const int g = lane >> 2, q = lane & 3;
    const int i0 = blockIdx.x * 64;
    const int sn = t >> 2, sq = t & 3;

#pragma unroll
    for (int cc = 0; cc < 8; cc++) {
        const int c8 = sq + cc * 4;
        const uint4* src = (const uint4*)(g_WT + (size_t)sn * (IN_DIM / 2) + c8 * 8);
        uint4 v0 = src[0], v1 = src[1];
        uint32_t* dst = B_sm + c8 * 512 + sn * 8;
        dst[0] = v0.x; dst[2] = v0.y; dst[4] = v0.z; dst[6] = v0.w;
        dst[1] = v1.x; dst[3] = v1.y; dst[5] = v1.z; dst[7] = v1.w;
    }

    float c[8][4];
#pragma unroll
    for (int tl = 0; tl < 8; tl++)
#pragma unroll
        for (int k = 0; k < 4; k++) c[tl][k] = 0.f;

    for (int it = 0; it < 4; it++) {
        __syncthreads();
#pragma unroll
        for (int qq = 0; qq < 8; qq++) {
            const int idx = t + 256 * qq;
            const int seg = idx >> 10;
            const int r   = (idx >> 4) & 63;
            const int c4  = (idx & 15) * 4;
            const float4 v = *(const float4*)&X[(size_t)(i0 + r) * IN_DIM
                                                + seg * 256 + it * 64 + c4];
            uint32_t* xd = Xs + (seg * 64 + r) * GXS_STR + (c4 >> 1);
            xd[0] = pack_f16(v.x, v.y);
            xd[1] = pack_f16(v.z, v.w);
        }
        __syncthreads();

        const uint32_t* xrA = Xs + (grp * 64 + woff + g) * GXS_STR;
        const uint32_t* xrB = xrA + 8 * GXS_STR;
#pragma unroll
        for (int s = 0; s < 4; s++) {
            const int kw = s * 8;
            const uint32_t a0 = xrA[kw + q];
            const uint32_t a2 = xrA[kw + 4 + q];
            const uint32_t a1 = xrB[kw + q];
            const uint32_t a3 = xrB[kw + 4 + q];
            const int gstep = grp * 16 + it * 4 + s;
            const uint32_t* Bp = B_sm + gstep * 512 + g * 8 + q * 2;
#pragma unroll
            for (int tl = 0; tl < 8; tl++) {
                uint2 bb = *(const uint2*)(Bp + tl * 64);
                asm volatile(
                    "mma.sync.aligned.m16n8k16.row.col.f32.f16.f16.f32 "
                    "{%0,%1,%2,%3}, {%4,%5,%6,%7}, {%8,%9}, {%0,%1,%2,%3};"
                    : "+f"(c[tl][0]), "+f"(c[tl][1]), "+f"(c[tl][2]), "+f"(c[tl][3])
                    : "r"(a0), "r"(a1), "r"(a2), "r"(a3), "r"(bb.x), "r"(bb.y));
            }
        }
    }

    __syncthreads();
    float* red = (float*)dsm;
    if (grp == 1) {
        float* p = red + ((size_t)((wid - 4) * 32 + lane)) * 32;
#pragma unroll
        for (int tl = 0; tl < 8; tl++)
#pragma unroll
            for (int k = 0; k < 4; k++) p[tl * 4 + k] = c[tl][k];
    }
    __syncthreads();
    if (grp == 0) {
        const float* p = red + ((size_t)(wid * 32 + lane)) * 32;
#pragma unroll
        for (int tl = 0; tl < 8; tl++)
#pragma unroll
            for (int k = 0; k < 4; k++) c[tl][k] += p[tl * 4 + k];
        const int iA = i0 + woff + g, iB = iA + 8;
#pragma unroll
        for (int tl = 0; tl < 8; tl++) {
            const int col = tl * 8 + 2 * q;
            *(float2*)&g_h[(size_t)iA * OUT_DIM + col] = make_float2(c[tl][0], c[tl][1]);
            *(float2*)&g_h[(size_t)iB * OUT_DIM + col] = make_float2(c[tl][2], c[tl][3]);
        }
    }
}

// ---------------------------------------------------------------------------
// Kernel 2: SMEM transpose h -> g_hT (fp16), s1/s2 scores, global max(s2).
// ---------------------------------------------------------------------------
__global__ __launch_bounds__(256) void score_T_kernel(const float* __restrict__ a) {
    __shared__ __align__(16) float hs[64][68];
    const int t = threadIdx.x, i0 = blockIdx.x * 64;
    {
        const int r = t >> 2, c0 = (t & 3) * 16;
#pragma unroll
        for (int q = 0; q < 4; q++)
            *(float4*)&hs[r][c0 + q * 4] =
                *(const float4*)&g_h[(size_t)(i0 + r) * OUT_DIM + c0 + q * 4];
    }
    __syncthreads();
    {
        const int d = t >> 2, ibs = (t & 3) * 16;
        uint32_t* dst = (uint32_t*)g_hT + ((size_t)d * N_NODES + i0 + ibs) / 2;
#pragma unroll
        for (int k = 0; k < 8; k++)
            dst[k] = pack_f16(hs[ibs + 2 * k][d], hs[ibs + 2 * k + 1][d]);
    }
    {
        const int w = t >> 5, lane = t & 31;
#pragma unroll
        for (int rr = 0; rr < 8; rr++) {
            const int row = w * 8 + rr;
            float v0 = hs[row][lane], v1 = hs[row][lane + 32];
            float p1 = v0 * a[lane]      + v1 * a[lane + 32];
            float p2 = v0 * a[64 + lane] + v1 * a[96 + lane];
#pragma unroll
            for (int off = 16; off; off >>= 1) {
                p1 += __shfl_down_sync(0xffffffffu, p1, off);
                p2 += __shfl_down_sync(0xffffffffu, p2, off);
            }
            if (lane == 0) {
                g_s1[i0 + row] = p1;
                g_s2[i0 + row] = p2;
                atomicMax(&g_s2max_u, encf(p2));
            }
        }
    }
}

// ---------------------------------------------------------------------------
// Kernel 3: fused masked-softmax attention, fp16 mma.sync.m16n8k16.
// R13 ballot/prefetch scheme + TRUE double-buffered B/s2 with ONE
// __syncthreads per chunk: masks(ch) -> sync -> stage buf[ch+1] -> compute ch.
// grid 256: blockIdx = ib*2 + jh; CTA = 64 i-rows x 4096 j (jh half).
// ---------------------------------------------------------------------------
__global__ __launch_bounds__(256, 2) void attn_f16_kernel(const int* __restrict__ Adj) {
    // [0..8191]: B double buffer (2 x 4096 w); [8192..8447]: s2 double buffer.
    __shared__ __align__(16) float smem_buf[8448];
    uint32_t* B_sm = (uint32_t*)smem_buf;

    const int t = threadIdx.x, lane = t & 31, wid = t >> 5;
    const int ib = blockIdx.x >> 1, jh = blockIdx.x & 1;
    const int i0 = ib * 64, jbase = jh * 4096;
    const int grp = wid >> 2, woff = (wid & 3) * 16;
    const int g = lane >> 2, l4 = lane & 3;
    const int iA = i0 + woff + g, iB = iA + 8;

    const float s1a = g_s1[iA] * LOG2E;
    const float s1b = g_s1[iB] * LOG2E;
    const float s2m = decf(g_s2max_u) * LOG2E;
    float bA = s1a + s2m; bA = fmaxf(bA, ALPHA * bA);
    float bB = s1b + s2m; bB = fmaxf(bB, ALPHA * bB);
    const float kA = fmaxf(0.f, bA - 14.f);
    const float kB = fmaxf(0.f, bB - 14.f);
    const float aA = s1a - kA, cA = fmaf(ALPHA, s1a, -kA);
    const float aB = s1b - kB, cB = fmaf(ALPHA, s1b, -kB);

    const uint32_t bitlo = 1u << l4;
    const uint32_t bithi = 16u << l4;

    float c[8][4];
#pragma unroll
    for (int tl = 0; tl < 8; tl++)
#pragma unroll
        for (int k = 0; k < 4; k++) c[tl][k] = 0.f;
    float esA = 0.f, esB = 0.f;

    const uint32_t* hT32 = (const uint32_t*)g_hT;
    const int sn = t >> 2, sq = t & 3;

    // B/s2 staging helper (buffer bsel, chunk at j0c)
    auto stage = [&](int bsel, int j0c) {
#pragma unroll
        for (int cc = 0; cc < 2; cc++) {
            const int c8 = sq + cc * 4;
            const uint4* src = (const uint4*)(hT32 + (size_t)sn * (N_NODES / 2)
                                              + (size_t)(j0c + c8 * 16) / 2);
            uint4 v0 = src[0], v1 = src[1];
            uint32_t* dst = B_sm + (bsel << 12) + c8 * 512 + sn * 8;
            dst[0] = v0.x; dst[2] = v0.y; dst[4] = v0.z; dst[6] = v0.w;
            dst[1] = v1.x; dst[3] = v1.y; dst[5] = v1.z; dst[7] = v1.w;
        }
        if (t < 128) smem_buf[8192 + (bsel << 7) + t] = g_s2[j0c + t] * LOG2E;
    };

    // ---- prologue: stage chunk 0 into buffer 0 ----
    stage(0, jbase);

    for (int ch = 0; ch < 32; ch++) {
        const int b  = ch & 1;
        const int j0 = jbase + ch * 128;

        // ---- Adj masks for this chunk (prefetch 8x2 + ballots; overlaps barrier) ----
        uint32_t mAe = 0, mAo = 0, mBe = 0, mBo = 0;
        {
            const size_t jg = (size_t)j0 + grp * 64 + 2 * lane;
            const int rowbase = i0 + woff;
            int2 v[8];
#pragma unroll
            for (int r = 0; r < 8; r++)
                v[r] = *(const int2*)(Adj + (size_t)(rowbase + r) * N_NODES + jg);
#pragma unroll
            for (int r = 0; r < 8; r++) {
                uint32_t be = __ballot_sync(0xffffffffu, v[r].x != 0);
                uint32_t bo = __ballot_sync(0xffffffffu, v[r].y != 0);
                if (g == r) { mAe = be; mAo = bo; }
            }
#pragma unroll
            for (int r = 0; r < 8; r++)
                v[r] = *(const int2*)(Adj + (size_t)(rowbase + 8 + r) * N_NODES + jg);
#pragma unroll
            for (int r = 0; r < 8; r++) {
                uint32_t be = __ballot_sync(0xffffffffu, v[r].x != 0);
                uint32_t bo = __ballot_sync(0xffffffffu, v[r].y != 0);
                if (g == r) { mBe = be; mBo = bo; }
            }
        }

        // ONE barrier per chunk: orders stage(buf b, prev iter) -> compute(ch),
        // and compute(ch-1) -> stage(buf b^1, below) which reuses ch-1's buffer.
        __syncthreads();

        // ---- stage next chunk into the other buffer ----
        if (ch < 31) stage(b ^ 1, j0 + 128);

        // ---- 4 steps of 16 j: E in A-fragment regs, 8 MMAs over d ----
#pragma unroll
        for (int s = 0; s < 4; s++) {
            const float* s2p = smem_buf + 8192 + (b << 7) + grp * 64 + s * 16;
            float2 sA = *(const float2*)(s2p + 2 * l4);
            float2 sB = *(const float2*)(s2p + 2 * l4 + 8);
            const uint32_t blo = bitlo << (s * 8);
            const uint32_t bhi = bithi << (s * 8);

            float e00, e01, e02, e03, e10, e11, e12, e13;
            e00 = (mAe & blo) ? ex2f(fmaxf(aA + sA.x, fmaf(ALPHA, sA.x, cA))) : 0.f;
            e01 = (mAo & blo) ? ex2f(fmaxf(aA + sA.y, fmaf(ALPHA, sA.y, cA))) : 0.f;
            e02 = (mAe & bhi) ? ex2f(fmaxf(aA + sB.x, fmaf(ALPHA, sB.x, cA))) : 0.f;
            e03 = (mAo & bhi) ? ex2f(fmaxf(aA + sB.y, fmaf(ALPHA, sB.y, cA))) : 0.f;
            e10 = (mBe & blo) ? ex2f(fmaxf(aB + sA.x, fmaf(ALPHA, sA.x, cB))) : 0.f;
            e11 = (mBo & blo) ? ex2f(fmaxf(aB + sA.y, fmaf(ALPHA, sA.y, cB))) : 0.f;
            e12 = (mBe & bhi) ? ex2f(fmaxf(aB + sB.x, fmaf(ALPHA, sB.x, cB))) : 0.f;
            e13 = (mBo & bhi) ? ex2f(fmaxf(aB + sB.y, fmaf(ALPHA, sB.y, cB))) : 0.f;
            esA += (e00 + e01) + (e02 + e03);
            esB += (e10 + e11) + (e12 + e13);

            const uint32_t a0 = pack_f16(e00, e01);
            const uint32_t a1 = pack_f16(e10, e11);
            const uint32_t a2 = pack_f16(e02, e03);
            const uint32_t a3 = pack_f16(e12, e13);

            const uint32_t* Bp = B_sm + (b << 12) + (grp * 4 + s) * 512 + g * 8 + l4 * 2;
#pragma unroll
            for (int tl = 0; tl < 8; tl++) {
                uint2 bb = *(const uint2*)(Bp + tl * 64);
                asm volatile(
                    "mma.sync.aligned.m16n8k16.row.col.f32.f16.f16.f32 "
                    "{%0,%1,%2,%3}, {%4,%5,%6,%7}, {%8,%9}, {%0,%1,%2,%3};"
                    : "+f"(c[tl][0]), "+f"(c[tl][1]), "+f"(c[tl][2]), "+f"(c[tl][3])
                    : "r"(a0), "r"(a1), "r"(a2), "r"(a3), "r"(bb.x), "r"(bb.y));
            }
        }
    }

    // ---- merge grp1 into grp0 via SMEM (alias over staging area) ----
    __syncthreads();
    float* red = smem_buf;
    if (grp == 1) {
        float* p = red + ((size_t)((wid - 4) * 32 + lane)) * 34;
#pragma unroll
        for (int tl = 0; tl < 8; tl++)
#pragma unroll
            for (int k = 0; k < 4; k++) p[tl * 4 + k] = c[tl][k];
        p[32] = esA; p[33] = esB;
    }
    __syncthreads();
    if (grp == 0) {
        const float* p = red + ((size_t)(wid * 32 + lane)) * 34;
#pragma unroll
        for (int tl = 0; tl < 8; tl++)
#pragma unroll
            for (int k = 0; k < 4; k++) c[tl][k] += p[tl * 4 + k];
        esA += p[32]; esB += p[33];

        esA += __shfl_xor_sync(0xffffffffu, esA, 1);
        esA += __shfl_xor_sync(0xffffffffu, esA, 2);
        esB += __shfl_xor_sync(0xffffffffu, esB, 1);
        esB += __shfl_xor_sync(0xffffffffu, esB, 2);
        if (l4 == 0) {
            g_pes[(size_t)jh * N_NODES + iA] = esA;
            g_pes[(size_t)jh * N_NODES + iB] = esB;
        }
        float* outA = g_pD + ((size_t)jh * N_NODES + iA) * OUT_DIM;
        float* outB = g_pD + ((size_t)jh * N_NODES + iB) * OUT_DIM;
#pragma unroll
        for (int tl = 0; tl < 8; tl++) {
            *(float2*)(outA + tl * 8 + 2 * l4) = make_float2(c[tl][0], c[tl][1]);
            *(float2*)(outB + tl * 8 + 2 * l4) = make_float2(c[tl][2], c[tl][3]);
        }
    }
}

// ---------------------------------------------------------------------------
// Kernel 4: merge j-halves and normalize. Warp per row.
// ---------------------------------------------------------------------------
__global__ __launch_bounds__(256) void merge_kernel(float* __restrict__ out) {
    const int row  = blockIdx.x * 8 + (threadIdx.x >> 5);
    const int lane = threadIdx.x & 31;
    const float inv = 1.f / (g_pes[row] + g_pes[N_NODES + row]);
    const size_t o = (size_t)row * OUT_DIM + lane * 2;
    float2 v0 = *(const float2*)(g_pD + o);
    float2 v1 = *(const float2*)(g_pD + (size_t)N_NODES * OUT_DIM + o);
    *(float2*)(out + o) = make_float2((v0.x + v1.x) * inv, (v0.y + v1.y) * inv);
}

// ---------------------------------------------------------------------------
extern "C" void kernel_launch(void* const* d_in, const int* in_sizes, int n_in,
                              void* d_out, int out_size) {
    const float* X = nullptr; const int* Adj = nullptr;
    const float* W = nullptr; const float* a = nullptr;
    for (int k = 0; k < n_in; k++) {
        switch (in_sizes[k]) {
            case N_NODES * IN_DIM:  X   = (const float*)d_in[k]; break;
            case N_NODES * N_NODES: Adj = (const int*)d_in[k];   break;
            case IN_DIM * OUT_DIM:  W   = (const float*)d_in[k]; break;
            case 2 * OUT_DIM:       a   = (const float*)d_in[k]; break;
        }
    }

    static bool attr_set = false;
    if (!attr_set) {
        cudaFuncSetAttribute(gemm_f16_kernel,
                             cudaFuncAttributeMaxDynamicSharedMemorySize, GSMEM_B);
        attr_set = true;
    }

    wt_prep_kernel<<<64, 256>>>(W);
    gemm_f16_kernel<<<N_NODES / 64, 256, GSMEM_B>>>(X);
    score_T_kernel<<<N_NODES / 64, 256>>>(a);
    attn_f16_kernel<<<256, 256>>>(Adj);
    merge_kernel<<<N_NODES / 8, 256>>>((float*)d_out);
}

// round 16
// speedup vs baseline: 1.1705x; 1.1509x over previous
#include <cuda_runtime.h>
#include <cuda_fp16.h>
#include <cstddef>
#include <cstdint>

#define N_NODES 8192
#define IN_DIM  512
#define OUT_DIM 64
#define ALPHA   0.2f
#define LOG2E   1.4426950408889634f

// ---------------- scratch (no allocations allowed) ----------------
__device__ __align__(16) float    g_h [N_NODES * OUT_DIM];       // h = X @ W (f32)
__device__ __align__(16) uint32_t g_hB[(N_NODES / 16) * 512];    // h^T fp16, MMA-fragment order
__device__ __align__(16) uint32_t g_WT[OUT_DIM * IN_DIM / 2];    // W^T fp16 pair-packed
__device__ __align__(16) float    g_s1[N_NODES];
__device__ __align__(16) float    g_s2[N_NODES];
__device__ __align__(16) float    g_pD [2 * N_NODES * OUT_DIM];  // [jh][row][col]
__device__ __align__(16) float    g_pes[2 * N_NODES];            // [jh][row]
__device__ unsigned               g_s2max_u;                     // enc(max_j s2)

__device__ __forceinline__ uint32_t pack_f16(float lo, float hi) {
    uint32_t r;
    asm("cvt.rn.f16x2.f32 %0, %1, %2;" : "=r"(r) : "f"(hi), "f"(lo));
    return r;
}
__device__ __forceinline__ float ex2f(float x) {
    float r;
    asm("ex2.approx.f32 %0, %1;" : "=f"(r) : "f"(x));
    return r;
}
__device__ __forceinline__ unsigned encf(float f) {
    unsigned u = __float_as_uint(f);
    return (u & 0x80000000u) ? ~u : (u | 0x80000000u);
}
__device__ __forceinline__ float decf(unsigned u) {
    return (u & 0x80000000u) ? __uint_as_float(u & 0x7FFFFFFFu)
                             : __uint_as_float(~u);
}

// ---------------------------------------------------------------------------
// Kernel 0: pack W^T into fp16 pairs along k. Also resets g_s2max_u.
// ---------------------------------------------------------------------------
__global__ __launch_bounds__(256) void wt_prep_kernel(const float* __restrict__ W) {
    const int t = threadIdx.x;
    const int d = t & 63, k2 = blockIdx.x * 4 + (t >> 6);
    float lo = W[(size_t)(2 * k2) * OUT_DIM + d];
    float hi = W[(size_t)(2 * k2 + 1) * OUT_DIM + d];
    g_WT[(size_t)d * (IN_DIM / 2) + k2] = pack_f16(lo, hi);
    if (blockIdx.x == 0 && t == 0) g_s2max_u = 0u;
}

// ---------------------------------------------------------------------------
// Kernel 1: h = X @ W on fp16 mma.sync.m16n8k16 (unchanged from R13).
// ---------------------------------------------------------------------------
#define GXS_OFF  16384
#define GXS_STR  36
#define GSMEM_W  (16384 + 2 * 64 * GXS_STR)
#define GSMEM_B  (GSMEM_W * 4)

__global__ __launch_bounds__(256) void gemm_f16_kernel(const float* __restrict__ X) {
    extern __shared__ __align__(16) uint32_t dsm[];
    uint32_t* B_sm = dsm;
    uint32_t* Xs   = dsm + GXS_OFF;

    const int t = threadIdx.x, lane = t & 31, wid = t >> 5;
    const int grp = wid >> 2, woff = (wid & 3) * 16;
    const int g = lane >> 2, q = lane & 3;
    const int i0 = blockIdx.x * 64;
    const int sn = t >> 2, sq = t & 3;

#pragma unroll
    for (int cc = 0; cc < 8; cc++) {
        const int c8 = sq + cc * 4;
        const uint4* src = (const uint4*)(g_WT + (size_t)sn * (IN_DIM / 2) + c8 * 8);
        uint4 v0 = src[0], v1 = src[1];
        uint32_t* dst = B_sm + c8 * 512 + sn * 8;
        dst[0] = v0.x; dst[2] = v0.y; dst[4] = v0.z; dst[6] = v0.w;
        dst[1] = v1.x; dst[3] = v1.y; dst[5] = v1.z; dst[7] = v1.w;
    }

    float c[8][4];
#pragma unroll
    for (int tl = 0; tl < 8; tl++)
#pragma unroll
        for (int k = 0; k < 4; k++) c[tl][k] = 0.f;

    for (int it = 0; it < 4; it++) {
        __syncthreads();
#pragma unroll
        for (int qq = 0; qq < 8; qq++) {
            const int idx = t + 256 * qq;
            const int seg = idx >> 10;
            const int r   = (idx >> 4) & 63;
            const int c4  = (idx & 15) * 4;
            const float4 v = *(const float4*)&X[(size_t)(i0 + r) * IN_DIM
                                                + seg * 256 + it * 64 + c4];
            uint32_t* xd = Xs + (seg * 64 + r) * GXS_STR + (c4 >> 1);
            xd[0] = pack_f16(v.x, v.y);
            xd[1] = pack_f16(v.z, v.w);
        }
        __syncthreads();

        const uint32_t* xrA = Xs + (grp * 64 + woff + g) * GXS_STR;
        const uint32_t* xrB = xrA + 8 * GXS_STR;
#pragma unroll
        for (int s = 0; s < 4; s++) {
            const int kw = s * 8;
            const uint32_t a0 = xrA[kw + q];
            const uint32_t a2 = xrA[kw + 4 + q];
            const uint32_t a1 = xrB[kw + q];
            const uint32_t a3 = xrB[kw + 4 + q];
            const int gstep = grp * 16 + it * 4 + s;
            const uint32_t* Bp = B_sm + gstep * 512 + g * 8 + q * 2;
#pragma unroll
            for (int tl = 0; tl < 8; tl++) {
                uint2 bb = *(const uint2*)(Bp + tl * 64);
                asm volatile(
                    "mma.sync.aligned.m16n8k16.row.col.f32.f16.f16.f32 "
                    "{%0,%1,%2,%3}, {%4,%5,%6,%7}, {%8,%9}, {%0,%1,%2,%3};"
                    : "+f"(c[tl][0]), "+f"(c[tl][1]), "+f"(c[tl][2]), "+f"(c[tl][3])
                    : "r"(a0), "r"(a1), "r"(a2), "r"(a3), "r"(bb.x), "r"(bb.y));
            }
        }
    }

    __syncthreads();
    float* red = (float*)dsm;
    if (grp == 1) {
        float* p = red + ((size_t)((wid - 4) * 32 + lane)) * 32;
#pragma unroll
        for (int tl = 0; tl < 8; tl++)
#pragma unroll
            for (int k = 0; k < 4; k++) p[tl * 4 + k] = c[tl][k];
    }
    __syncthreads();
    if (grp == 0) {
        const float* p = red + ((size_t)(wid * 32 + lane)) * 32;
#pragma unroll
        for (int tl = 0; tl < 8; tl++)
#pragma unroll
            for (int k = 0; k < 4; k++) c[tl][k] += p[tl * 4 + k];
        const int iA = i0 + woff + g, iB = iA + 8;
#pragma unroll
        for (int tl = 0; tl < 8; tl++) {
            const int col = tl * 8 + 2 * q;
            *(float2*)&g_h[(size_t)iA * OUT_DIM + col] = make_float2(c[tl][0], c[tl][1]);
            *(float2*)&g_h[(size_t)iB * OUT_DIM + col] = make_float2(c[tl][2], c[tl][3]);
        }
    }
}

// ---------------------------------------------------------------------------
// Kernel 2: SMEM transpose h -> g_hB (fp16, MMA-FRAGMENT order in gmem),
// s1/s2 scores, global max(s2).
// g_hB word index: (i>>4)*512 + d*8 + k', where word k' holds the fp16 pair
// (i_local, i_local+1): pairs (0,1)(2,3)(4,5)(6,7) -> k'=0,2,4,6 and
// (8,9)(10,11)(12,13)(14,15) -> k'=1,3,5,7 (matches the MMA B-frag reads).
// ---------------------------------------------------------------------------
__global__ __launch_bounds__(256) void score_T_kernel(const float* __restrict__ a) {
    __shared__ __align__(16) float hs[64][68];
    const int t = threadIdx.x, i0 = blockIdx.x * 64;
    {
        const int r = t >> 2, c0 = (t & 3) * 16;
#pragma unroll
        for (int q = 0; q < 4; q++)
            *(float4*)&hs[r][c0 + q * 4] =
                *(const float4*)&g_h[(size_t)(i0 + r) * OUT_DIM + c0 + q * 4];
    }
    __syncthreads();
    {
        const int d = t >> 2, ibs = (t & 3) * 16;
        uint32_t* dst = g_hB + ((size_t)(i0 + ibs) >> 4) * 512 + d * 8;
#pragma unroll
        for (int k = 0; k < 8; k++) {
            const int kp = (k < 4) ? (2 * k) : (2 * (k - 4) + 1);
            dst[kp] = pack_f16(hs[ibs + 2 * k][d], hs[ibs + 2 * k + 1][d]);
        }
    }
    {
        const int w = t >> 5, lane = t & 31;
#pragma unroll
        for (int rr = 0; rr < 8; rr++) {
            const int row = w * 8 + rr;
            float v0 = hs[row][lane], v1 = hs[row][lane + 32];
            float p1 = v0 * a[lane]      + v1 * a[lane + 32];
            float p2 = v0 * a[64 + lane] + v1 * a[96 + lane];
#pragma unroll
            for (int off = 16; off; off >>= 1) {
                p1 += __shfl_down_sync(0xffffffffu, p1, off);
                p2 += __shfl_down_sync(0xffffffffu, p2, off);
            }
            if (lane == 0) {
                g_s1[i0 + row] = p1;
                g_s2[i0 + row] = p2;
                atomicMax(&g_s2max_u, encf(p2));
            }
        }
    }
}

// ---------------------------------------------------------------------------
// Kernel 3: fused masked-softmax attention, fp16 mma.sync.m16n8k16.
// R13 structure; ONLY change: B staging is now a pure contiguous copy from
// fragment-ordered g_hB (4x LDG.128 + 4x conflict-free STS.128 per thread).
// grid 256: blockIdx = ib*2 + jh; CTA = 64 i-rows x 4096 j (jh half).
// ---------------------------------------------------------------------------
__global__ __launch_bounds__(256, 2) void attn_f16_kernel(const int* __restrict__ Adj) {
    __shared__ __align__(16) float smem_buf[4352];   // B_sm(4096 w) + s2(128); aliased red
    uint32_t* B_sm  = (uint32_t*)smem_buf;
    float*    s2_sm = smem_buf + 4096;

    const int t = threadIdx.x, lane = t & 31, wid = t >> 5;
    const int ib = blockIdx.x >> 1, jh = blockIdx.x & 1;
    const int i0 = ib * 64, jbase = jh * 4096;
    const int grp = wid >> 2, woff = (wid & 3) * 16;
    const int g = lane >> 2, l4 = lane & 3;
    const int iA = i0 + woff + g, iB = iA + 8;

    const float s1a = g_s1[iA] * LOG2E;
    const float s1b = g_s1[iB] * LOG2E;
    const float s2m = decf(g_s2max_u) * LOG2E;
    float bA = s1a + s2m; bA = fmaxf(bA, ALPHA * bA);
    float bB = s1b + s2m; bB = fmaxf(bB, ALPHA * bB);
    const float kA = fmaxf(0.f, bA - 14.f);
    const float kB = fmaxf(0.f, bB - 14.f);
    const float aA = s1a - kA, cA = fmaf(ALPHA, s1a, -kA);
    const float aB = s1b - kB, cB = fmaf(ALPHA, s1b, -kB);

    const uint32_t bitlo = 1u << l4;
    const uint32_t bithi = 16u << l4;

    float c[8][4];
#pragma unroll
    for (int tl = 0; tl < 8; tl++)
#pragma unroll
        for (int k = 0; k < 4; k++) c[tl][k] = 0.f;
    float esA = 0.f, esB = 0.f;

    for (int ch = 0; ch < 32; ch++) {
        const int j0 = jbase + ch * 128;

        // ---- Adj masks: two 8-row prefetch batches (MLP=8), then ballots ----
        uint32_t mAe = 0, mAo = 0, mBe = 0, mBo = 0;
        {
            const size_t jg = (size_t)j0 + grp * 64 + 2 * lane;
            const int rowbase = i0 + woff;
            int2 v[8];
#pragma unroll
            for (int r = 0; r < 8; r++)
                v[r] = *(const int2*)(Adj + (size_t)(rowbase + r) * N_NODES + jg);
#pragma unroll
            for (int r = 0; r < 8; r++) {
                uint32_t be = __ballot_sync(0xffffffffu, v[r].x != 0);
                uint32_t bo = __ballot_sync(0xffffffffu, v[r].y != 0);
                if (g == r) { mAe = be; mAo = bo; }
            }
#pragma unroll
            for (int r = 0; r < 8; r++)
                v[r] = *(const int2*)(Adj + (size_t)(rowbase + 8 + r) * N_NODES + jg);
#pragma unroll
            for (int r = 0; r < 8; r++) {
                uint32_t be = __ballot_sync(0xffffffffu, v[r].x != 0);
                uint32_t bo = __ballot_sync(0xffffffffu, v[r].y != 0);
                if (g == r) { mBe = be; mBo = bo; }
            }
        }
        __syncthreads();   // previous chunk's B consumption complete

        // ---- stage B: contiguous copy (fragment order precomputed in g_hB) ----
        {
            const uint4* src = (const uint4*)(g_hB + ((size_t)j0 >> 4) * 512);
            uint4* dst = (uint4*)B_sm;
#pragma unroll
            for (int q = 0; q < 4; q++)
                dst[t + 256 * q] = src[t + 256 * q];
        }
        if (t < 128) s2_sm[t] = g_s2[j0 + t] * LOG2E;
        __syncthreads();

        // ---- 4 steps of 16 j: E in A-fragment regs, 8 MMAs over d ----
#pragma unroll
        for (int s = 0; s < 4; s++) {
            const float* s2p = s2_sm + grp * 64 + s * 16;
            float2 sA = *(const float2*)(s2p + 2 * l4);
            float2 sB = *(const float2*)(s2p + 2 * l4 + 8);
            const uint32_t blo = bitlo << (s * 8);
            const uint32_t bhi = bithi << (s * 8);

            float e00, e01, e02, e03, e10, e11, e12, e13;
            e00 = (mAe & blo) ? ex2f(fmaxf(aA + sA.x, fmaf(ALPHA, sA.x, cA))) : 0.f;
            e01 = (mAo & blo) ? ex2f(fmaxf(aA + sA.y, fmaf(ALPHA, sA.y, cA))) : 0.f;
            e02 = (mAe & bhi) ? ex2f(fmaxf(aA + sB.x, fmaf(ALPHA, sB.x, cA))) : 0.f;
            e03 = (mAo & bhi) ? ex2f(fmaxf(aA + sB.y, fmaf(ALPHA, sB.y, cA))) : 0.f;
            e10 = (mBe & blo) ? ex2f(fmaxf(aB + sA.x, fmaf(ALPHA, sA.x, cB))) : 0.f;
            e11 = (mBo & blo) ? ex2f(fmaxf(aB + sA.y, fmaf(ALPHA, sA.y, cB))) : 0.f;
            e12 = (mBe & bhi) ? ex2f(fmaxf(aB + sB.x, fmaf(ALPHA, sB.x, cB))) : 0.f;
            e13 = (mBo & bhi) ? ex2f(fmaxf(aB + sB.y, fmaf(ALPHA, sB.y, cB))) : 0.f;
            esA += (e00 + e01) + (e02 + e03);
            esB += (e10 + e11) + (e12 + e13);

            const uint32_t a0 = pack_f16(e00, e01);
            const uint32_t a1 = pack_f16(e10, e11);
            const uint32_t a2 = pack_f16(e02, e03);
            const uint32_t a3 = pack_f16(e12, e13);

            const uint32_t* Bp = B_sm + (grp * 4 + s) * 512 + g * 8 + l4 * 2;
#pragma unroll
            for (int tl = 0; tl < 8; tl++) {
                uint2 bb = *(const uint2*)(Bp + tl * 64);
                asm volatile(
                    "mma.sync.aligned.m16n8k16.row.col.f32.f16.f16.f32 "
                    "{%0,%1,%2,%3}, {%4,%5,%6,%7}, {%8,%9}, {%0,%1,%2,%3};"
                    : "+f"(c[tl][0]), "+f"(c[tl][1]), "+f"(c[tl][2]), "+f"(c[tl][3])
                    : "r"(a0), "r"(a1), "r"(a2), "r"(a3), "r"(bb.x), "r"(bb.y));
            }
        }
    }

    // ---- merge grp1 into grp0 via SMEM (alias over staging area) ----
    __syncthreads();
    float* red = smem_buf;
    if (grp == 1) {
        float* p = red + ((size_t)((wid - 4) * 32 + lane)) * 34;
#pragma unroll
        for (int tl = 0; tl < 8; tl++)
#pragma unroll
            for (int k = 0; k < 4; k++) p[tl * 4 + k] = c[tl][k];
        p[32] = esA; p[33] = esB;
    }
    __syncthreads();
    if (grp == 0) {
        const float* p = red + ((size_t)(wid * 32 + lane)) * 34;
#pragma unroll
        for (int tl = 0; tl < 8; tl++)
#pragma unroll
            for (int k = 0; k < 4; k++) c[tl][k] += p[tl * 4 + k];
        esA += p[32]; esB += p[33];

        esA += __shfl_xor_sync(0xffffffffu, esA, 1);
        esA += __shfl_xor_sync(0xffffffffu, esA, 2);
        esB += __shfl_xor_sync(0xffffffffu, esB, 1);
        esB += __shfl_xor_sync(0xffffffffu, esB, 2);
        if (l4 == 0) {
            g_pes[(size_t)jh * N_NODES + iA] = esA;
            g_pes[(size_t)jh * N_NODES + iB] = esB;
        }
        float* outA = g_pD + ((size_t)jh * N_NODES + iA) * OUT_DIM;
        float* outB = g_pD + ((size_t)jh * N_NODES + iB) * OUT_DIM;
#pragma unroll
        for (int tl = 0; tl < 8; tl++) {
            *(float2*)(outA + tl * 8 + 2 * l4) = make_float2(c[tl][0], c[tl][1]);
            *(float2*)(outB + tl * 8 + 2 * l4) = make_float2(c[tl][2], c[tl][3]);
        }
    }
}

// ---------------------------------------------------------------------------
// Kernel 4: merge j-halves and normalize. Warp per row.
// ---------------------------------------------------------------------------
__global__ __launch_bounds__(256) void merge_kernel(float* __restrict__ out) {
    const int row  = blockIdx.x * 8 + (threadIdx.x >> 5);
    const int lane = threadIdx.x & 31;
    const float inv = 1.f / (g_pes[row] + g_pes[N_NODES + row]);
    const size_t o = (size_t)row * OUT_DIM + lane * 2;
    float2 v0 = *(const float2*)(g_pD + o);
    float2 v1 = *(const float2*)(g_pD + (size_t)N_NODES * OUT_DIM + o);
    *(float2*)(out + o) = make_float2((v0.x + v1.x) * inv, (v0.y + v1.y) * inv);
}

// ---------------------------------------------------------------------------
extern "C" void kernel_launch(void* const* d_in, const int* in_sizes, int n_in,
                              void* d_out, int out_size) {
    const float* X = nullptr; const int* Adj = nullptr;
    const float* W = nullptr; const float* a = nullptr;
    for (int k = 0; k < n_in; k++) {
        switch (in_sizes[k]) {
            case N_NODES * IN_DIM:  X   = (const float*)d_in[k]; break;
            case N_NODES * N_NODES: Adj = (const int*)d_in[k];   break;
            case IN_DIM * OUT_DIM:  W   = (const float*)d_in[k]; break;
            case 2 * OUT_DIM:       a   = (const float*)d_in[k]; break;
        }
    }

    static bool attr_set = false;
    if (!attr_set) {
        cudaFuncSetAttribute(gemm_f16_kernel,
                             cudaFuncAttributeMaxDynamicSharedMemorySize, GSMEM_B);
        attr_set = true;
    }

    wt_prep_kernel<<<64, 256>>>(W);
    gemm_f16_kernel<<<N_NODES / 64, 256, GSMEM_B>>>(X);
    score_T_kernel<<<N_NODES / 64, 256>>>(a);
    attn_f16_kernel<<<256, 256>>>(Adj);
    merge_kernel<<<N_NODES / 8, 256>>>((float*)d_out);
}

// round 17
// speedup vs baseline: 1.3099x; 1.1191x over previous
#include <cuda_runtime.h>
#include <cuda_fp16.h>
#include <cstddef>
#include <cstdint>

#define N_NODES 8192
#define IN_DIM  512
#define OUT_DIM 64
#define ALPHA   0.2f
#define LOG2E   1.4426950408889634f

// ---------------- scratch (no allocations allowed) ----------------
__device__ __align__(16) float    g_h [N_NODES * OUT_DIM];       // h = X @ W (f32)
__device__ __align__(16) uint32_t g_hB[(N_NODES / 16) * 512];    // h^T fp16, MMA-fragment order
__device__ __align__(16) uint32_t g_WT[OUT_DIM * IN_DIM / 2];    // W^T fp16 pair-packed
__device__ __align__(16) float    g_s1[N_NODES];
__device__ __align__(16) float    g_s2[N_NODES];
__device__ __align__(16) float    g_pD [2 * N_NODES * OUT_DIM];  // [jh][row][col]
__device__ __align__(16) float    g_pes[2 * N_NODES];            // [jh][row]
__device__ unsigned               g_s2max_u;                     // enc(max_j s2)

__device__ __forceinline__ uint32_t pack_f16(float lo, float hi) {
    uint32_t r;
    asm("cvt.rn.f16x2.f32 %0, %1, %2;" : "=r"(r) : "f"(hi), "f"(lo));
    return r;
}
__device__ __forceinline__ float ex2f(float x) {
    float r;
    asm("ex2.approx.f32 %0, %1;" : "=f"(r) : "f"(x));
    return r;
}
__device__ __forceinline__ unsigned encf(float f) {
    unsigned u = __float_as_uint(f);
    return (u & 0x80000000u) ? ~u : (u | 0x80000000u);
}
__device__ __forceinline__ float decf(unsigned u) {
    return (u & 0x80000000u) ? __uint_as_float(u & 0x7FFFFFFFu)
                             : __uint_as_float(~u);
}

// ---------------------------------------------------------------------------
// Kernel 0: pack W^T into fp16 pairs along k. Also resets g_s2max_u.
// ---------------------------------------------------------------------------
__global__ __launch_bounds__(256) void wt_prep_kernel(const float* __restrict__ W) {
    const int t = threadIdx.x;
    const int d = t & 63, k2 = blockIdx.x * 4 + (t >> 6);
    float lo = W[(size_t)(2 * k2) * OUT_DIM + d];
    float hi = W[(size_t)(2 * k2 + 1) * OUT_DIM + d];
    g_WT[(size_t)d * (IN_DIM / 2) + k2] = pack_f16(lo, hi);
    if (blockIdx.x == 0 && t == 0) g_s2max_u = 0u;
}

// ---------------------------------------------------------------------------
// Kernel 1: h = X @ W on fp16 mma.sync.m16n8k16 (unchanged from R16).
// ---------------------------------------------------------------------------
#define GXS_OFF  16384
#define GXS_STR  36
#define GSMEM_W  (16384 + 2 * 64 * GXS_STR)
#define GSMEM_B  (GSMEM_W * 4)

__global__ __launch_bounds__(256) void gemm_f16_kernel(const float* __restrict__ X) {
    extern __shared__ __align__(16) uint32_t dsm[];
    uint32_t* B_sm = dsm;
    uint32_t* Xs   = dsm + GXS_OFF;

    const int t = threadIdx.x, lane = t & 31, wid = t >> 5;
    const int grp = wid >> 2, woff = (wid & 3) * 16;
    const int g = lane >> 2, q = lane & 3;
    const int i0 = blockIdx.x * 64;
    const int sn = t >> 2, sq = t & 3;

#pragma unroll
    for (int cc = 0; cc < 8; cc++) {
        const int c8 = sq + cc * 4;
        const uint4* src = (const uint4*)(g_WT + (size_t)sn * (IN_DIM / 2) + c8 * 8);
        uint4 v0 = src[0], v1 = src[1];
        uint32_t* dst = B_sm + c8 * 512 + sn * 8;
        dst[0] = v0.x; dst[2] = v0.y; dst[4] = v0.z; dst[6] = v0.w;
        dst[1] = v1.x; dst[3] = v1.y; dst[5] = v1.z; dst[7] = v1.w;
    }

    float c[8][4];
#pragma unroll
    for (int tl = 0; tl < 8; tl++)
#pragma unroll
        for (int k = 0; k < 4; k++) c[tl][k] = 0.f;

    for (int it = 0; it < 4; it++) {
        __syncthreads();
#pragma unroll
        for (int qq = 0; qq < 8; qq++) {
            const int idx = t + 256 * qq;
            const int seg = idx >> 10;
            const int r   = (idx >> 4) & 63;
            const int c4  = (idx & 15) * 4;
            const float4 v = *(const float4*)&X[(size_t)(i0 + r) * IN_DIM
                                                + seg * 256 + it * 64 + c4];
            uint32_t* xd = Xs + (seg * 64 + r) * GXS_STR + (c4 >> 1);
            xd[0] = pack_f16(v.x, v.y);
            xd[1] = pack_f16(v.z, v.w);
        }
        __syncthreads();

        const uint32_t* xrA = Xs + (grp * 64 + woff + g) * GXS_STR;
        const uint32_t* xrB = xrA + 8 * GXS_STR;
#pragma unroll
        for (int s = 0; s < 4; s++) {
            const int kw = s * 8;
            const uint32_t a0 = xrA[kw + q];
            const uint32_t a2 = xrA[kw + 4 + q];
            const uint32_t a1 = xrB[kw + q];
            const uint32_t a3 = xrB[kw + 4 + q];
            const int gstep = grp * 16 + it * 4 + s;
            const uint32_t* Bp = B_sm + gstep * 512 + g * 8 + q * 2;
#pragma unroll
            for (int tl = 0; tl < 8; tl++) {
                uint2 bb = *(const uint2*)(Bp + tl * 64);
                asm volatile(
                    "mma.sync.aligned.m16n8k16.row.col.f32.f16.f16.f32 "
                    "{%0,%1,%2,%3}, {%4,%5,%6,%7}, {%8,%9}, {%0,%1,%2,%3};"
                    : "+f"(c[tl][0]), "+f"(c[tl][1]), "+f"(c[tl][2]), "+f"(c[tl][3])
                    : "r"(a0), "r"(a1), "r"(a2), "r"(a3), "r"(bb.x), "r"(bb.y));
            }
        }
    }

    __syncthreads();
    float* red = (float*)dsm;
    if (grp == 1) {
        float* p = red + ((size_t)((wid - 4) * 32 + lane)) * 32;
#pragma unroll
        for (int tl = 0; tl < 8; tl++)
#pragma unroll
            for (int k = 0; k < 4; k++) p[tl * 4 + k] = c[tl][k];
    }
    __syncthreads();
    if (grp == 0) {
        const float* p = red + ((size_t)(wid * 32 + lane)) * 32;
#pragma unroll
        for (int tl = 0; tl < 8; tl++)
#pragma unroll
            for (int k = 0; k < 4; k++) c[tl][k] += p[tl * 4 + k];
        const int iA = i0 + woff + g, iB = iA + 8;
#pragma unroll
        for (int tl = 0; tl < 8; tl++) {
            const int col = tl * 8 + 2 * q;
            *(float2*)&g_h[(size_t)iA * OUT_DIM + col] = make_float2(c[tl][0], c[tl][1]);
            *(float2*)&g_h[(size_t)iB * OUT_DIM + col] = make_float2(c[tl][2], c[tl][3]);
        }
    }
}

// ---------------------------------------------------------------------------
// Kernel 2: SMEM transpose h -> g_hB (fragment order), s1/s2, max(s2).
// (unchanged from R16)
// ---------------------------------------------------------------------------
__global__ __launch_bounds__(256) void score_T_kernel(const float* __restrict__ a) {
    __shared__ __align__(16) float hs[64][68];
    const int t = threadIdx.x, i0 = blockIdx.x * 64;
    {
        const int r = t >> 2, c0 = (t & 3) * 16;
#pragma unroll
        for (int q = 0; q < 4; q++)
            *(float4*)&hs[r][c0 + q * 4] =
                *(const float4*)&g_h[(size_t)(i0 + r) * OUT_DIM + c0 + q * 4];
    }
    __syncthreads();
    {
        const int d = t >> 2, ibs = (t & 3) * 16;
        uint32_t* dst = g_hB + ((size_t)(i0 + ibs) >> 4) * 512 + d * 8;
#pragma unroll
        for (int k = 0; k < 8; k++) {
            const int kp = (k < 4) ? (2 * k) : (2 * (k - 4) + 1);
            dst[kp] = pack_f16(hs[ibs + 2 * k][d], hs[ibs + 2 * k + 1][d]);
        }
    }
    {
        const int w = t >> 5, lane = t & 31;
#pragma unroll
        for (int rr = 0; rr < 8; rr++) {
            const int row = w * 8 + rr;
            float v0 = hs[row][lane], v1 = hs[row][lane + 32];
            float p1 = v0 * a[lane]      + v1 * a[lane + 32];
            float p2 = v0 * a[64 + lane] + v1 * a[96 + lane];
#pragma unroll
            for (int off = 16; off; off >>= 1) {
                p1 += __shfl_down_sync(0xffffffffu, p1, off);
                p2 += __shfl_down_sync(0xffffffffu, p2, off);
            }
            if (lane == 0) {
                g_s1[i0 + row] = p1;
                g_s2[i0 + row] = p2;
                atomicMax(&g_s2max_u, encf(p2));
            }
        }
    }
}

// ---------------------------------------------------------------------------
// Kernel 3: fused masked-softmax attention, fp16 mma.sync.m16n8k16.
// CHANGE vs R16: exp FACTORED out of the inner loop. Per-row constants
// E1=exp2(s1L-k), E2=exp2(a*s1L-k), T=exp2(-s1L); per-j staged pair
// (F1,F2)=(exp2(s2L), exp2(a*s2L)). Inner E = FSETP+FSEL+FMUL (no MUFU):
//   e = adj ? ((F1>T) ? F1*E1 : F2*E2) : 0     [exact same value as before]
// ---------------------------------------------------------------------------
__global__ __launch_bounds__(256, 2) void attn_f16_kernel(const int* __restrict__ Adj) {
    __shared__ __align__(16) float smem_buf[4352];   // B_sm(4096 w) + F_sm(256); aliased red
    uint32_t* B_sm = (uint32_t*)smem_buf;
    float*    F_sm = smem_buf + 4096;                // [j_local][2] = (F1, F2)

    const int t = threadIdx.x, lane = t & 31, wid = t >> 5;
    const int ib = blockIdx.x >> 1, jh = blockIdx.x & 1;
    const int i0 = ib * 64, jbase = jh * 4096;
    const int grp = wid >> 2, woff = (wid & 3) * 16;
    const int g = lane >> 2, l4 = lane & 3;
    const int iA = i0 + woff + g, iB = iA + 8;

    const float s1a = g_s1[iA] * LOG2E;
    const float s1b = g_s1[iB] * LOG2E;
    const float s2m = decf(g_s2max_u) * LOG2E;
    float bA = s1a + s2m; bA = fmaxf(bA, ALPHA * bA);
    float bB = s1b + s2m; bB = fmaxf(bB, ALPHA * bB);
    const float kA = fmaxf(0.f, bA - 14.f);
    const float kB = fmaxf(0.f, bB - 14.f);
    // factored per-row constants
    const float E1A = ex2f(s1a - kA), E2A = ex2f(fmaf(ALPHA, s1a, -kA)), TA = ex2f(-s1a);
    const float E1B = ex2f(s1b - kB), E2B = ex2f(fmaf(ALPHA, s1b, -kB)), TB = ex2f(-s1b);

    const uint32_t bitlo = 1u << l4;
    const uint32_t bithi = 16u << l4;

    float c[8][4];
#pragma unroll
    for (int tl = 0; tl < 8; tl++)
#pragma unroll
        for (int k = 0; k < 4; k++) c[tl][k] = 0.f;
    float esA = 0.f, esB = 0.f;

    for (int ch = 0; ch < 32; ch++) {
        const int j0 = jbase + ch * 128;

        // ---- Adj masks: two 8-row prefetch batches (MLP=8), then ballots ----
        uint32_t mAe = 0, mAo = 0, mBe = 0, mBo = 0;
        {
            const size_t jg = (size_t)j0 + grp * 64 + 2 * lane;
            const int rowbase = i0 + woff;
            int2 v[8];
#pragma unroll
            for (int r = 0; r < 8; r++)
                v[r] = *(const int2*)(Adj + (size_t)(rowbase + r) * N_NODES + jg);
#pragma unroll
            for (int r = 0; r < 8; r++) {
                uint32_t be = __ballot_sync(0xffffffffu, v[r].x != 0);
                uint32_t bo = __ballot_sync(0xffffffffu, v[r].y != 0);
                if (g == r) { mAe = be; mAo = bo; }
            }
#pragma unroll
            for (int r = 0; r < 8; r++)
                v[r] = *(const int2*)(Adj + (size_t)(rowbase + 8 + r) * N_NODES + jg);
#pragma unroll
            for (int r = 0; r < 8; r++) {
                uint32_t be = __ballot_sync(0xffffffffu, v[r].x != 0);
                uint32_t bo = __ballot_sync(0xffffffffu, v[r].y != 0);
                if (g == r) { mBe = be; mBo = bo; }
            }
        }
        __syncthreads();   // previous chunk's B consumption complete

        // ---- stage B: contiguous copy (fragment order precomputed in g_hB) ----
        {
            const uint4* src = (const uint4*)(g_hB + ((size_t)j0 >> 4) * 512);
            uint4* dst = (uint4*)B_sm;
#pragma unroll
            for (int q = 0; q < 4; q++)
                dst[t + 256 * q] = src[t + 256 * q];
        }
        // ---- stage F pairs: (exp2(s2L), exp2(a*s2L)) per j ----
        if (t < 128) {
            const float s2v = g_s2[j0 + t] * LOG2E;
            *(float2*)&F_sm[2 * t] = make_float2(ex2f(s2v), ex2f(ALPHA * s2v));
        }
        __syncthreads();

        // ---- 4 steps of 16 j: E via factored products, 8 MMAs over d ----
#pragma unroll
        for (int s = 0; s < 4; s++) {
            const float* Fp = F_sm + (grp * 64 + s * 16) * 2;
            const float4 fa = *(const float4*)(Fp + 4 * l4);        // j, j+1
            const float4 fb = *(const float4*)(Fp + 4 * l4 + 16);   // j+8, j+9
            const uint32_t blo = bitlo << (s * 8);
            const uint32_t bhi = bithi << (s * 8);

            float e00, e01, e02, e03, e10, e11, e12, e13;
            e00 = (mAe & blo) ? ((fa.x > TA) ? fa.x * E1A : fa.y * E2A) : 0.f;
            e01 = (mAo & blo) ? ((fa.z > TA) ? fa.z * E1A : fa.w * E2A) : 0.f;
            e02 = (mAe & bhi) ? ((fb.x > TA) ? fb.x * E1A : fb.y * E2A) : 0.f;
            e03 = (mAo & bhi) ? ((fb.z > TA) ? fb.z * E1A : fb.w * E2A) : 0.f;
            e10 = (mBe & blo) ? ((fa.x > TB) ? fa.x * E1B : fa.y * E2B) : 0.f;
            e11 = (mBo & blo) ? ((fa.z > TB) ? fa.z * E1B : fa.w * E2B) : 0.f;
            e12 = (mBe & bhi) ? ((fb.x > TB) ? fb.x * E1B : fb.y * E2B) : 0.f;
            e13 = (mBo & bhi) ? ((fb.z > TB) ? fb.z * E1B : fb.w * E2B) : 0.f;
            esA += (e00 + e01) + (e02 + e03);
            esB += (e10 + e11) + (e12 + e13);

            const uint32_t a0 = pack_f16(e00, e01);
            const uint32_t a1 = pack_f16(e10, e11);
            const uint32_t a2 = pack_f16(e02, e03);
            const uint32_t a3 = pack_f16(e12, e13);

            const uint32_t* Bp = B_sm + (grp * 4 + s) * 512 + g * 8 + l4 * 2;
#pragma unroll
            for (int tl = 0; tl < 8; tl++) {
                uint2 bb = *(const uint2*)(Bp + tl * 64);
                asm volatile(
                    "mma.sync.aligned.m16n8k16.row.col.f32.f16.f16.f32 "
                    "{%0,%1,%2,%3}, {%4,%5,%6,%7}, {%8,%9}, {%0,%1,%2,%3};"
                    : "+f"(c[tl][0]), "+f"(c[tl][1]), "+f"(c[tl][2]), "+f"(c[tl][3])
                    : "r"(a0), "r"(a1), "r"(a2), "r"(a3), "r"(bb.x), "r"(bb.y));
            }
        }
    }

    // ---- merge grp1 into grp0 via SMEM (alias over staging area) ----
    __syncthreads();
    float* red = smem_buf;
    if (grp == 1) {
        float* p = red + ((size_t)((wid - 4) * 32 + lane)) * 34;
#pragma unroll
        for (int tl = 0; tl < 8; tl++)
#pragma unroll
            for (int k = 0; k < 4; k++) p[tl * 4 + k] = c[tl][k];
        p[32] = esA; p[33] = esB;
    }
    __syncthreads();
    if (grp == 0) {
        const float* p = red + ((size_t)(wid * 32 + lane)) * 34;
#pragma unroll
        for (int tl = 0; tl < 8; tl++)
#pragma unroll
            for (int k = 0; k < 4; k++) c[tl][k] += p[tl * 4 + k];
        esA += p[32]; esB += p[33];

        esA += __shfl_xor_sync(0xffffffffu, esA, 1);
        esA += __shfl_xor_sync(0xffffffffu, esA, 2);
        esB += __shfl_xor_sync(0xffffffffu, esB, 1);
        esB += __shfl_xor_sync(0xffffffffu, esB, 2);
        if (l4 == 0) {
            g_pes[(size_t)jh * N_NODES + iA] = esA;
            g_pes[(size_t)jh * N_NODES + iB] = esB;
        }
        float* outA = g_pD + ((size_t)jh * N_NODES + iA) * OUT_DIM;
        float* outB = g_pD + ((size_t)jh * N_NODES + iB) * OUT_DIM;
#pragma unroll
        for (int tl = 0; tl < 8; tl++) {
            *(float2*)(outA + tl * 8 + 2 * l4) = make_float2(c[tl][0], c[tl][1]);
            *(float2*)(outB + tl * 8 + 2 * l4) = make_float2(c[tl][2], c[tl][3]);
        }
    }
}

// ---------------------------------------------------------------------------
// Kernel 4: merge j-halves and normalize. Warp per row.
// ---------------------------------------------------------------------------
__global__ __launch_bounds__(256) void merge_kernel(float* __restrict__ out) {
    const int row  = blockIdx.x * 8 + (threadIdx.x >> 5);
    const int lane = threadIdx.x & 31;
    const float inv = 1.f / (g_pes[row] + g_pes[N_NODES + row]);
    const size_t o = (size_t)row * OUT_DIM + lane * 2;
    float2 v0 = *(const float2*)(g_pD + o);
    float2 v1 = *(const float2*)(g_pD + (size_t)N_NODES * OUT_DIM + o);
    *(float2*)(out + o) = make_float2((v0.x + v1.x) * inv, (v0.y + v1.y) * inv);
}

// ---------------------------------------------------------------------------
extern "C" void kernel_launch(void* const* d_in, const int* in_sizes, int n_in,
                              void* d_out, int out_size) {
    const float* X = nullptr; const int* Adj = nullptr;
    const float* W = nullptr; const float* a = nullptr;
    for (int k = 0; k < n_in; k++) {
        switch (in_sizes[k]) {
            case N_NODES * IN_DIM:  X   = (const float*)d_in[k]; break;
            case N_NODES * N_NODES: Adj = (const int*)d_in[k];   break;
            case IN_DIM * OUT_DIM:  W   = (const float*)d_in[k]; break;
            case 2 * OUT_DIM:       a   = (const float*)d_in[k]; break;
        }
    }

    static bool attr_set = false;
    if (!attr_set) {
        cudaFuncSetAttribute(gemm_f16_kernel,
                             cudaFuncAttributeMaxDynamicSharedMemorySize, GSMEM_B);
        attr_set = true;
    }

    wt_prep_kernel<<<64, 256>>>(W);
    gemm_f16_kernel<<<N_NODES / 64, 256, GSMEM_B>>>(X);
    score_T_kernel<<<N_NODES / 64, 256>>>(a);
    attn_f16_kernel<<<256, 256>>>(Adj);
    merge_kernel<<<N_NODES / 8, 256>>>((float*)d_out);
}